// round 2
// baseline (speedup 1.0000x reference)
#include <cuda_runtime.h>
#include <cuda_bf16.h>

#define NN 100000
#define EE 1600000
#define IN_DIM 128
#define HID 32
#define HEADS 4
#define OUT_DIM 40
#define NEG_SLOPE 0.2f

#define G1_ROWS 64
#define G1_SMEM ((IN_DIM*IN_DIM + G1_ROWS*IN_DIM) * (int)sizeof(float))
#define SCAN_B 1024
#define NB ((NN + SCAN_B - 1) / SCAN_B)   // 98

// ---------------- scratch (device globals: allocation-free) ----------------
__device__ float g_feat1[NN * IN_DIM];          // [N,4,32] layer-1 projected feats
__device__ float g_el1[NN * HEADS];
__device__ float g_er1[NN * HEADS];
__device__ float g_h1[NN * IN_DIM];             // relu(agg1) = layer-2 input
__device__ float g_feat2[NN * OUT_DIM];
__device__ float g_el2[NN];
__device__ float g_er2[NN];
__device__ int   g_deg[NN];
__device__ int   g_cnt[NN];
__device__ int   g_rowptr[NN + 1];
__device__ int   g_esrc[EE];                    // edge sources grouped by dst
__device__ int   g_bsum[128];
__device__ int   g_boff[128];

// ---------------- zero deg/cnt ----------------
__global__ void zero_kernel() {
    int i = blockIdx.x * blockDim.x + threadIdx.x;
    if (i < NN) { g_deg[i] = 0; g_cnt[i] = 0; }
}

// ---------------- GEMM1: feat1 = h @ W1  (64-row tiles, smem W + H) -------
__global__ __launch_bounds__(256) void gemm1_kernel(const float* __restrict__ h,
                                                    const float* __restrict__ W1) {
    extern __shared__ float sm[];
    float* Ws = sm;                     // 128*128
    float* Hs = sm + IN_DIM * IN_DIM;   // G1_ROWS*128
    int t = threadIdx.x;
    int row0 = blockIdx.x * G1_ROWS;

    const float4* W4 = (const float4*)W1;
    float4* Ws4 = (float4*)Ws;
    for (int i = t; i < IN_DIM * IN_DIM / 4; i += 256) Ws4[i] = W4[i];

    float4* Hs4 = (float4*)Hs;
    const float4* H4 = (const float4*)h;
    for (int i = t; i < G1_ROWS * IN_DIM / 4; i += 256) {
        int r = i >> 5;            // row within tile (32 float4 per row)
        int c = i & 31;
        int g = row0 + r;
        Hs4[i] = (g < NN) ? H4[g * 32 + c] : make_float4(0.f, 0.f, 0.f, 0.f);
    }
    __syncthreads();

    int cg = t & 31;   // col group: cols cg*4..cg*4+3
    int rg = t >> 5;   // row group: rows rg*8..rg*8+7
    float4 acc[8];
    #pragma unroll
    for (int r = 0; r < 8; ++r) acc[r] = make_float4(0.f, 0.f, 0.f, 0.f);

    #pragma unroll 4
    for (int k = 0; k < IN_DIM; ++k) {
        float4 w = ((const float4*)(Ws + k * IN_DIM))[cg];
        #pragma unroll
        for (int r = 0; r < 8; ++r) {
            float hv = Hs[(rg * 8 + r) * IN_DIM + k];
            acc[r].x += hv * w.x; acc[r].y += hv * w.y;
            acc[r].z += hv * w.z; acc[r].w += hv * w.w;
        }
    }

    for (int r = 0; r < 8; ++r) {
        int g = row0 + rg * 8 + r;
        if (g < NN) ((float4*)g_feat1)[g * 32 + cg] = acc[r];
    }
}

// ---------------- el1/er1: per-(node,head) attention logits ---------------
__global__ void elr1_kernel(const float* __restrict__ al1, const float* __restrict__ ar1) {
    int w = (blockIdx.x * blockDim.x + threadIdx.x) >> 5;
    int l = threadIdx.x & 31;
    if (w >= NN) return;
    float4 f = ((const float4*)g_feat1)[w * 32 + l];   // feat dims 4l..4l+3
    int hh = l >> 3, j = l & 7;
    float4 a = ((const float4*)al1)[hh * 8 + j];
    float4 b = ((const float4*)ar1)[hh * 8 + j];
    float el = f.x * a.x + f.y * a.y + f.z * a.z + f.w * a.w;
    float er = f.x * b.x + f.y * b.y + f.z * b.z + f.w * b.w;
    el += __shfl_xor_sync(0xFFFFFFFFu, el, 1);
    el += __shfl_xor_sync(0xFFFFFFFFu, el, 2);
    el += __shfl_xor_sync(0xFFFFFFFFu, el, 4);
    er += __shfl_xor_sync(0xFFFFFFFFu, er, 1);
    er += __shfl_xor_sync(0xFFFFFFFFu, er, 2);
    er += __shfl_xor_sync(0xFFFFFFFFu, er, 4);
    if (j == 0) { g_el1[w * 4 + hh] = el; g_er1[w * 4 + hh] = er; }
}

// ---------------- CSR build ----------------
__global__ void hist_kernel(const int* __restrict__ dst) {
    int i = blockIdx.x * blockDim.x + threadIdx.x;
    if (i < EE) atomicAdd(&g_deg[dst[i]], 1);
}

__global__ void scan1_kernel() {
    __shared__ int s[SCAN_B];
    int tid = threadIdx.x;
    int i = blockIdx.x * SCAN_B + tid;
    int v = (i < NN) ? g_deg[i] : 0;
    s[tid] = v;
    __syncthreads();
    for (int off = 1; off < SCAN_B; off <<= 1) {
        int x = (tid >= off) ? s[tid - off] : 0;
        __syncthreads();
        s[tid] += x;
        __syncthreads();
    }
    if (i < NN) g_rowptr[i] = s[tid] - v;      // exclusive within block
    if (tid == SCAN_B - 1) g_bsum[blockIdx.x] = s[tid];
}

__global__ void scan2_kernel() {
    if (threadIdx.x == 0) {
        int acc = 0;
        for (int b = 0; b < NB; ++b) { g_boff[b] = acc; acc += g_bsum[b]; }
    }
}

__global__ void scan3_kernel() {
    int i = blockIdx.x * SCAN_B + threadIdx.x;
    if (i < NN) g_rowptr[i] += g_boff[blockIdx.x];
    if (i == 0) g_rowptr[NN] = EE;
}

__global__ void scatter_kernel(const int* __restrict__ src, const int* __restrict__ dst) {
    int i = blockIdx.x * blockDim.x + threadIdx.x;
    if (i < EE) {
        int d = dst[i];
        int pos = g_rowptr[d] + atomicAdd(&g_cnt[d], 1);
        g_esrc[pos] = src[i];
    }
}

// ---------------- layer-1 aggregation: warp per node ----------------
__global__ void agg1_kernel(const float* __restrict__ b1) {
    int n = (blockIdx.x * blockDim.x + threadIdx.x) >> 5;
    int l = threadIdx.x & 31;
    if (n >= NN) return;
    int hh = l >> 3;
    float erh = g_er1[n * 4 + hh];
    int s0 = g_rowptr[n], s1 = g_rowptr[n + 1];

    float dsum = 0.f;
    for (int i = s0; i < s1; ++i) {
        int s = g_esrc[i];
        float e = g_el1[s * 4 + hh] + erh;
        e = fmaxf(e, NEG_SLOPE * e);           // leaky_relu (0<slope<1)
        dsum += __expf(e);
    }
    float inv = 1.0f / fmaxf(dsum, 1e-9f);

    float4 acc = make_float4(0.f, 0.f, 0.f, 0.f);
    const float4* f4 = (const float4*)g_feat1;
    for (int i = s0; i < s1; ++i) {
        int s = g_esrc[i];
        float e = g_el1[s * 4 + hh] + erh;
        e = fmaxf(e, NEG_SLOPE * e);
        float w = __expf(e);
        float4 f = f4[s * 32 + l];
        acc.x += w * f.x; acc.y += w * f.y; acc.z += w * f.z; acc.w += w * f.w;
    }
    float4 bb = ((const float4*)b1)[l];
    float4 o;
    o.x = fmaxf(acc.x * inv + bb.x, 0.f);
    o.y = fmaxf(acc.y * inv + bb.y, 0.f);
    o.z = fmaxf(acc.z * inv + bb.z, 0.f);
    o.w = fmaxf(acc.w * inv + bb.w, 0.f);
    ((float4*)g_h1)[n * 32 + l] = o;
}

// ---------------- GEMM2 + el2/er2: warp per row ----------------
#define G2_ROWS 8
__global__ __launch_bounds__(256) void gemm2_kernel(const float* __restrict__ W2,
                                                    const float* __restrict__ al2,
                                                    const float* __restrict__ ar2) {
    __shared__ float Ws[IN_DIM * OUT_DIM];    // 20KB
    __shared__ float Hs[G2_ROWS][IN_DIM];     // 4KB
    __shared__ float A2[OUT_DIM], R2[OUT_DIM];
    int t = threadIdx.x;
    for (int i = t; i < IN_DIM * OUT_DIM; i += 256) Ws[i] = W2[i];
    if (t < OUT_DIM) { A2[t] = al2[t]; R2[t] = ar2[t]; }
    int row0 = blockIdx.x * G2_ROWS;
    for (int i = t; i < G2_ROWS * IN_DIM / 4; i += 256) {
        int r = i >> 5, c = i & 31;
        int g = row0 + r;
        ((float4*)Hs)[i] = (g < NN) ? ((const float4*)g_h1)[g * 32 + c]
                                    : make_float4(0.f, 0.f, 0.f, 0.f);
    }
    __syncthreads();

    int wp = t >> 5, l = t & 31;
    int n = row0 + wp;
    float acc0 = 0.f, acc1 = 0.f;
    #pragma unroll 4
    for (int k = 0; k < IN_DIM; ++k) {
        float hv = Hs[wp][k];
        acc0 += hv * Ws[k * OUT_DIM + l];
        if (l < 8) acc1 += hv * Ws[k * OUT_DIM + 32 + l];
    }
    if (n < NN) {
        g_feat2[n * OUT_DIM + l] = acc0;
        if (l < 8) g_feat2[n * OUT_DIM + 32 + l] = acc1;
        float p = acc0 * A2[l] + ((l < 8) ? acc1 * A2[32 + l] : 0.f);
        float q = acc0 * R2[l] + ((l < 8) ? acc1 * R2[32 + l] : 0.f);
        #pragma unroll
        for (int off = 16; off >= 1; off >>= 1) {
            p += __shfl_xor_sync(0xFFFFFFFFu, p, off);
            q += __shfl_xor_sync(0xFFFFFFFFu, q, off);
        }
        if (l == 0) { g_el2[n] = p; g_er2[n] = q; }
    }
}

// ---------------- layer-2 aggregation: warp per node ----------------
__global__ void agg2_kernel(const float* __restrict__ b2, float* __restrict__ out) {
    int n = (blockIdx.x * blockDim.x + threadIdx.x) >> 5;
    int l = threadIdx.x & 31;
    if (n >= NN) return;
    float er = g_er2[n];
    int s0 = g_rowptr[n], s1 = g_rowptr[n + 1];

    float dsum = 0.f;
    for (int i = s0; i < s1; ++i) {
        int s = g_esrc[i];
        float e = g_el2[s] + er;
        e = fmaxf(e, NEG_SLOPE * e);
        dsum += __expf(e);
    }
    float inv = 1.0f / fmaxf(dsum, 1e-9f);

    float acc0 = 0.f, acc1 = 0.f;
    for (int i = s0; i < s1; ++i) {
        int s = g_esrc[i];
        float e = g_el2[s] + er;
        e = fmaxf(e, NEG_SLOPE * e);
        float w = __expf(e);
        acc0 += w * g_feat2[s * OUT_DIM + l];
        if (l < 8) acc1 += w * g_feat2[s * OUT_DIM + 32 + l];
    }
    out[n * OUT_DIM + l] = acc0 * inv + b2[l];
    if (l < 8) out[n * OUT_DIM + 32 + l] = acc1 * inv + b2[32 + l];
}

// ---------------- launch ----------------
extern "C" void kernel_launch(void* const* d_in, const int* in_sizes, int n_in,
                              void* d_out, int out_size) {
    const float* h   = (const float*)d_in[0];
    const int*   src = (const int*)  d_in[1];
    const int*   dst = (const int*)  d_in[2];
    const float* W1  = (const float*)d_in[3];
    const float* al1 = (const float*)d_in[4];
    const float* ar1 = (const float*)d_in[5];
    const float* b1  = (const float*)d_in[6];
    const float* W2  = (const float*)d_in[7];
    const float* al2 = (const float*)d_in[8];
    const float* ar2 = (const float*)d_in[9];
    const float* b2  = (const float*)d_in[10];
    float* out = (float*)d_out;

    cudaFuncSetAttribute(gemm1_kernel, cudaFuncAttributeMaxDynamicSharedMemorySize, G1_SMEM);

    int nwarp_blocks = (NN * 32 + 255) / 256;     // warp-per-node kernels
    int eblocks = (EE + 255) / 256;

    zero_kernel<<<(NN + 255) / 256, 256>>>();
    gemm1_kernel<<<(NN + G1_ROWS - 1) / G1_ROWS, 256, G1_SMEM>>>(h, W1);
    elr1_kernel<<<nwarp_blocks, 256>>>(al1, ar1);
    hist_kernel<<<eblocks, 256>>>(dst);
    scan1_kernel<<<NB, SCAN_B>>>();
    scan2_kernel<<<1, 32>>>();
    scan3_kernel<<<NB, SCAN_B>>>();
    scatter_kernel<<<eblocks, 256>>>(src, dst);
    agg1_kernel<<<nwarp_blocks, 256>>>(b1);
    gemm2_kernel<<<(NN + G2_ROWS - 1) / G2_ROWS, 256>>>(W2, al2, ar2);
    agg2_kernel<<<nwarp_blocks, 256>>>(b2, out);
}

// round 3
// speedup vs baseline: 1.4221x; 1.4221x over previous
#include <cuda_runtime.h>
#include <cuda_bf16.h>

#define NN 100000
#define EE 1600000
#define IN_DIM 128
#define HID 32
#define HEADS 4
#define OUT_DIM 40
#define NEG_SLOPE 0.2f

#define G1_ROWS 64
#define G1_SMEM ((IN_DIM*IN_DIM + G1_ROWS*IN_DIM) * (int)sizeof(float))
#define G2_ROWS 64
#define G2_HPAD 66
#define G2_SMEM ((IN_DIM*OUT_DIM + IN_DIM*G2_HPAD) * (int)sizeof(float))
#define SCAN_B 1024
#define NB ((NN + SCAN_B - 1) / SCAN_B)   // 98

typedef unsigned long long ull;

// ---------------- f32x2 packed-math helpers (sm_103a) ----------------
__device__ __forceinline__ ull pack2(float a, float b) {
    ull r; asm("mov.b64 %0,{%1,%2};" : "=l"(r) : "f"(a), "f"(b)); return r;
}
__device__ __forceinline__ void unpack2(ull p, float& a, float& b) {
    asm("mov.b64 {%0,%1},%2;" : "=f"(a), "=f"(b) : "l"(p));
}
__device__ __forceinline__ void ffma2(ull& acc, ull a, ull b) {
    asm("fma.rn.f32x2 %0,%1,%2,%0;" : "+l"(acc) : "l"(a), "l"(b));
}

// ---------------- scratch (device globals: allocation-free) ----------------
__device__ float g_feat1[NN * IN_DIM];
__device__ float g_el1[NN * HEADS];
__device__ float g_er1[NN * HEADS];
__device__ float g_h1[NN * IN_DIM];
__device__ float g_feat2[NN * OUT_DIM];
__device__ float g_el2[NN];
__device__ float g_er2[NN];
__device__ int   g_deg[NN];
__device__ int   g_rank[EE];
__device__ int   g_rowptr[NN + 1];
__device__ int   g_esrc[EE];
__device__ int   g_bsum[128];
__device__ int   g_boff[128];

// ---------------- zero deg ----------------
__global__ void zero_kernel() {
    int i = blockIdx.x * blockDim.x + threadIdx.x;
    if (i < NN) g_deg[i] = 0;
}

// ---------- GEMM1 + fused el1/er1: feat1 = h @ W1, f32x2 math ----------
__global__ __launch_bounds__(256) void gemm1_kernel(const float* __restrict__ h,
                                                    const float* __restrict__ W1,
                                                    const float* __restrict__ al1,
                                                    const float* __restrict__ ar1) {
    extern __shared__ float sm[];
    float* Ws = sm;                      // 128*128
    float* Hs = sm + IN_DIM * IN_DIM;    // 64*128
    int t = threadIdx.x;
    int row0 = blockIdx.x * G1_ROWS;

    const float4* W4 = (const float4*)W1;
    float4* Ws4 = (float4*)Ws;
    for (int i = t; i < IN_DIM * IN_DIM / 4; i += 256) Ws4[i] = W4[i];

    float4* Hs4 = (float4*)Hs;
    const float4* H4 = (const float4*)h;
    for (int i = t; i < G1_ROWS * IN_DIM / 4; i += 256) {
        int r = i >> 5, c = i & 31;
        int g = row0 + r;
        Hs4[i] = (g < NN) ? H4[g * 32 + c] : make_float4(0.f, 0.f, 0.f, 0.f);
    }
    __syncthreads();

    int cg = t & 31;   // lane: cols cg*4..cg*4+3
    int rg = t >> 5;   // warp: rows rg*8..rg*8+7
    ull acc[8][2];
    #pragma unroll
    for (int r = 0; r < 8; ++r) { acc[r][0] = 0ull; acc[r][1] = 0ull; }

    const float* Hrow = Hs + rg * 8 * IN_DIM;
    #pragma unroll 2
    for (int k = 0; k < IN_DIM; ++k) {
        float4 w = ((const float4*)(Ws + k * IN_DIM))[cg];
        ull wxy = pack2(w.x, w.y);
        ull wzw = pack2(w.z, w.w);
        #pragma unroll
        for (int r = 0; r < 8; ++r) {
            float hv = Hrow[r * IN_DIM + k];
            ull h2 = pack2(hv, hv);
            ffma2(acc[r][0], h2, wxy);
            ffma2(acc[r][1], h2, wzw);
        }
    }

    float4 al = ((const float4*)al1)[cg];
    float4 ar = ((const float4*)ar1)[cg];
    int hh = cg >> 3;

    #pragma unroll
    for (int r = 0; r < 8; ++r) {
        int g = row0 + rg * 8 + r;     // uniform across warp
        if (g >= NN) continue;
        float c0, c1, c2, c3;
        unpack2(acc[r][0], c0, c1);
        unpack2(acc[r][1], c2, c3);
        float4 o = make_float4(c0, c1, c2, c3);
        ((float4*)g_feat1)[g * 32 + cg] = o;
        float p = c0 * al.x + c1 * al.y + c2 * al.z + c3 * al.w;
        float q = c0 * ar.x + c1 * ar.y + c2 * ar.z + c3 * ar.w;
        p += __shfl_xor_sync(0xFFFFFFFFu, p, 1);
        p += __shfl_xor_sync(0xFFFFFFFFu, p, 2);
        p += __shfl_xor_sync(0xFFFFFFFFu, p, 4);
        q += __shfl_xor_sync(0xFFFFFFFFu, q, 1);
        q += __shfl_xor_sync(0xFFFFFFFFu, q, 2);
        q += __shfl_xor_sync(0xFFFFFFFFu, q, 4);
        if ((cg & 7) == 0) {
            g_el1[g * 4 + hh] = p;
            g_er1[g * 4 + hh] = q;
        }
    }
}

// ---------------- CSR build ----------------
__global__ void hist_kernel(const int* __restrict__ dst) {
    int i = blockIdx.x * blockDim.x + threadIdx.x;
    if (i < EE) g_rank[i] = atomicAdd(&g_deg[dst[i]], 1);
}

__global__ void scan1_kernel() {
    __shared__ int s[SCAN_B];
    int tid = threadIdx.x;
    int i = blockIdx.x * SCAN_B + tid;
    int v = (i < NN) ? g_deg[i] : 0;
    s[tid] = v;
    __syncthreads();
    for (int off = 1; off < SCAN_B; off <<= 1) {
        int x = (tid >= off) ? s[tid - off] : 0;
        __syncthreads();
        s[tid] += x;
        __syncthreads();
    }
    if (i < NN) g_rowptr[i] = s[tid] - v;
    if (tid == SCAN_B - 1) g_bsum[blockIdx.x] = s[tid];
}

__global__ void scan2_kernel() {    // 128 threads, scan NB=98 block sums
    int t = threadIdx.x;
    int lane = t & 31, wp = t >> 5;
    int v = (t < NB) ? g_bsum[t] : 0;
    int x = v;
    #pragma unroll
    for (int off = 1; off < 32; off <<= 1) {
        int y = __shfl_up_sync(0xFFFFFFFFu, x, off);
        if (lane >= off) x += y;
    }
    __shared__ int wsum[4];
    if (lane == 31) wsum[wp] = x;
    __syncthreads();
    int add = 0;
    for (int w = 0; w < wp; ++w) add += wsum[w];
    if (t < NB) g_boff[t] = x - v + add;   // exclusive
}

__global__ void scan3_kernel() {
    int i = blockIdx.x * SCAN_B + threadIdx.x;
    if (i < NN) g_rowptr[i] += g_boff[blockIdx.x];
    if (i == 0) g_rowptr[NN] = EE;
}

__global__ void scatter_kernel(const int* __restrict__ src, const int* __restrict__ dst) {
    int i = blockIdx.x * blockDim.x + threadIdx.x;
    if (i < EE) {
        int d = dst[i];
        g_esrc[g_rowptr[d] + g_rank[i]] = src[i];
    }
}

// ------- layer-1 aggregation: warp/node, SINGLE pass, 2-edge unroll -------
__global__ void agg1_kernel(const float* __restrict__ b1) {
    int n = (blockIdx.x * blockDim.x + threadIdx.x) >> 5;
    int l = threadIdx.x & 31;
    if (n >= NN) return;
    int hh = l >> 3;
    float erh = g_er1[n * 4 + hh];
    int s0 = g_rowptr[n], s1 = g_rowptr[n + 1];

    const ulonglong2* f2 = (const ulonglong2*)g_feat1;
    ull aA0 = 0, aA1 = 0, aB0 = 0, aB1 = 0;
    float dsA = 0.f, dsB = 0.f;

    int i = s0;
    for (; i + 2 <= s1; i += 2) {
        int sa = g_esrc[i];
        int sb = g_esrc[i + 1];
        float ea = g_el1[sa * 4 + hh] + erh;
        float eb = g_el1[sb * 4 + hh] + erh;
        ulonglong2 fa = f2[sa * 32 + l];
        ulonglong2 fb = f2[sb * 32 + l];
        ea = fmaxf(ea, NEG_SLOPE * ea);
        eb = fmaxf(eb, NEG_SLOPE * eb);
        float wa = __expf(ea);
        float wb = __expf(eb);
        ull wa2 = pack2(wa, wa), wb2 = pack2(wb, wb);
        ffma2(aA0, wa2, fa.x); ffma2(aA1, wa2, fa.y);
        ffma2(aB0, wb2, fb.x); ffma2(aB1, wb2, fb.y);
        dsA += wa; dsB += wb;
    }
    if (i < s1) {
        int sa = g_esrc[i];
        float ea = g_el1[sa * 4 + hh] + erh;
        ea = fmaxf(ea, NEG_SLOPE * ea);
        float wa = __expf(ea);
        ulonglong2 fa = f2[sa * 32 + l];
        ull wa2 = pack2(wa, wa);
        ffma2(aA0, wa2, fa.x); ffma2(aA1, wa2, fa.y);
        dsA += wa;
    }

    float inv = 1.0f / fmaxf(dsA + dsB, 1e-9f);
    float xA, yA, xB, yB, zA, wAv, zB, wBv;
    unpack2(aA0, xA, yA); unpack2(aB0, xB, yB);
    unpack2(aA1, zA, wAv); unpack2(aB1, zB, wBv);
    float4 bb = ((const float4*)b1)[l];
    float4 o;
    o.x = fmaxf((xA + xB) * inv + bb.x, 0.f);
    o.y = fmaxf((yA + yB) * inv + bb.y, 0.f);
    o.z = fmaxf((zA + wBv * 0.f + zB) * inv + bb.z, 0.f);   // (zA+zB)
    o.w = fmaxf((wAv + wBv) * inv + bb.w, 0.f);
    o.z = fmaxf((zA + zB) * inv + bb.z, 0.f);
    ((float4*)g_h1)[n * 32 + l] = o;
}

// ------- GEMM2 + fused el2/er2: f32x2, 8 rows/warp, transposed H tile -----
__global__ __launch_bounds__(256) void gemm2_kernel(const float* __restrict__ W2,
                                                    const float* __restrict__ al2,
                                                    const float* __restrict__ ar2) {
    extern __shared__ float sm[];
    float* Ws  = sm;                           // 128*40
    float* HsT = sm + IN_DIM * OUT_DIM;        // [k][r] padded stride 66
    int t = threadIdx.x;
    int row0 = blockIdx.x * G2_ROWS;

    for (int i = t; i < IN_DIM * OUT_DIM; i += 256) Ws[i] = W2[i];

    const float4* H4 = (const float4*)g_h1;
    for (int i = t; i < G2_ROWS * IN_DIM / 4; i += 256) {
        int r = i >> 5, c4 = i & 31;
        int g = row0 + r;
        float4 f = (g < NN) ? H4[g * 32 + c4] : make_float4(0.f, 0.f, 0.f, 0.f);
        HsT[(4 * c4 + 0) * G2_HPAD + r] = f.x;
        HsT[(4 * c4 + 1) * G2_HPAD + r] = f.y;
        HsT[(4 * c4 + 2) * G2_HPAD + r] = f.z;
        HsT[(4 * c4 + 3) * G2_HPAD + r] = f.w;
    }
    __syncthreads();

    int l = t & 31;
    int wr = (t >> 5) * 8;                     // warp's first row in tile
    bool hi = (l < 8);
    float a0 = __ldg(al2 + l), r0 = __ldg(ar2 + l);
    float a1 = hi ? __ldg(al2 + 32 + l) : 0.f;
    float r1 = hi ? __ldg(ar2 + 32 + l) : 0.f;

    ull acc[4][2];
    #pragma unroll
    for (int rp = 0; rp < 4; ++rp) { acc[rp][0] = 0ull; acc[rp][1] = 0ull; }

    #pragma unroll 2
    for (int k = 0; k < IN_DIM; ++k) {
        float w0 = Ws[k * OUT_DIM + l];
        float w1 = hi ? Ws[k * OUT_DIM + 32 + l] : 0.f;
        ull w02 = pack2(w0, w0), w12 = pack2(w1, w1);
        const ull* hp = (const ull*)(HsT + k * G2_HPAD + wr);
        #pragma unroll
        for (int rp = 0; rp < 4; ++rp) {
            ull h2 = hp[rp];
            ffma2(acc[rp][0], h2, w02);
            ffma2(acc[rp][1], h2, w12);
        }
    }

    #pragma unroll
    for (int rp = 0; rp < 4; ++rp) {
        float v0a, v0b, v1a, v1b;
        unpack2(acc[rp][0], v0a, v0b);
        unpack2(acc[rp][1], v1a, v1b);
        #pragma unroll
        for (int half = 0; half < 2; ++half) {
            int g = row0 + wr + 2 * rp + half;   // uniform per warp
            float v0 = half ? v0b : v0a;
            float v1 = half ? v1b : v1a;
            if (g < NN) {
                g_feat2[g * OUT_DIM + l] = v0;
                if (hi) g_feat2[g * OUT_DIM + 32 + l] = v1;
            }
            float p = v0 * a0 + v1 * a1;
            float q = v0 * r0 + v1 * r1;
            #pragma unroll
            for (int off = 16; off >= 1; off >>= 1) {
                p += __shfl_xor_sync(0xFFFFFFFFu, p, off);
                q += __shfl_xor_sync(0xFFFFFFFFu, q, off);
            }
            if (g < NN && l == 0) { g_el2[g] = p; g_er2[g] = q; }
        }
    }
}

// ------- layer-2 aggregation: warp/node, single pass, col-pairs -------
__global__ void agg2_kernel(const float* __restrict__ b2, float* __restrict__ out) {
    int n = (blockIdx.x * blockDim.x + threadIdx.x) >> 5;
    int l = threadIdx.x & 31;
    if (n >= NN) return;
    float er = g_er2[n];
    int s0 = g_rowptr[n], s1 = g_rowptr[n + 1];
    int lc = (l < 20) ? l : 19;          // lanes 20-31 shadow lane 19 (result unused)

    const ull* f2 = (const ull*)g_feat2;  // row = 20 ull
    ull aA = 0, aB = 0;
    float dsA = 0.f, dsB = 0.f;

    int i = s0;
    for (; i + 2 <= s1; i += 2) {
        int sa = g_esrc[i];
        int sb = g_esrc[i + 1];
        float ea = g_el2[sa] + er;
        float eb = g_el2[sb] + er;
        ull fa = f2[sa * 20 + lc];
        ull fb = f2[sb * 20 + lc];
        ea = fmaxf(ea, NEG_SLOPE * ea);
        eb = fmaxf(eb, NEG_SLOPE * eb);
        float wa = __expf(ea);
        float wb = __expf(eb);
        ffma2(aA, pack2(wa, wa), fa);
        ffma2(aB, pack2(wb, wb), fb);
        dsA += wa; dsB += wb;
    }
    if (i < s1) {
        int sa = g_esrc[i];
        float ea = g_el2[sa] + er;
        ea = fmaxf(ea, NEG_SLOPE * ea);
        float wa = __expf(ea);
        ffma2(aA, pack2(wa, wa), f2[sa * 20 + lc]);
        dsA += wa;
    }

    if (l < 20) {
        float inv = 1.0f / fmaxf(dsA + dsB, 1e-9f);
        float xa, ya, xb, yb;
        unpack2(aA, xa, ya); unpack2(aB, xb, yb);
        float o0 = (xa + xb) * inv + b2[2 * l];
        float o1 = (ya + yb) * inv + b2[2 * l + 1];
        ((ull*)out)[n * 20 + l] = pack2(o0, o1);
    }
}

// ---------------- launch ----------------
extern "C" void kernel_launch(void* const* d_in, const int* in_sizes, int n_in,
                              void* d_out, int out_size) {
    const float* h   = (const float*)d_in[0];
    const int*   src = (const int*)  d_in[1];
    const int*   dst = (const int*)  d_in[2];
    const float* W1  = (const float*)d_in[3];
    const float* al1 = (const float*)d_in[4];
    const float* ar1 = (const float*)d_in[5];
    const float* b1  = (const float*)d_in[6];
    const float* W2  = (const float*)d_in[7];
    const float* al2 = (const float*)d_in[8];
    const float* ar2 = (const float*)d_in[9];
    const float* b2  = (const float*)d_in[10];
    float* out = (float*)d_out;

    cudaFuncSetAttribute(gemm1_kernel, cudaFuncAttributeMaxDynamicSharedMemorySize, G1_SMEM);
    cudaFuncSetAttribute(gemm2_kernel, cudaFuncAttributeMaxDynamicSharedMemorySize, G2_SMEM);

    int nwarp_blocks = (NN * 32 + 255) / 256;
    int eblocks = (EE + 255) / 256;

    zero_kernel<<<(NN + 255) / 256, 256>>>();
    gemm1_kernel<<<(NN + G1_ROWS - 1) / G1_ROWS, 256, G1_SMEM>>>(h, W1, al1, ar1);
    hist_kernel<<<eblocks, 256>>>(dst);
    scan1_kernel<<<NB, SCAN_B>>>();
    scan2_kernel<<<1, 128>>>();
    scan3_kernel<<<NB, SCAN_B>>>();
    scatter_kernel<<<eblocks, 256>>>(src, dst);
    agg1_kernel<<<nwarp_blocks, 256>>>(b1);
    gemm2_kernel<<<(NN + G2_ROWS - 1) / G2_ROWS, 256, G2_SMEM>>>(W2, al2, ar2);
    agg2_kernel<<<nwarp_blocks, 256>>>(b2, out);
}